// round 16
// baseline (speedup 1.0000x reference)
#include <cuda_runtime.h>
#include <math.h>

#define H 128
#define LAYERS 4
#define NMAX 50176
#define EPS 1e-8f
#define FR 132   // fragment-pack stride in floats (2-way-conflict choice)

// ---------------- static device scratch (allocation-free rule) ----------------
__device__ float g_h[NMAX * H];
__device__ float g_A[NMAX * H];      // (h @ msgW1[0:128] + msgB1) -> indexed by dst
__device__ float g_B[NMAX * H];      // (h @ msgW1[128:256])       -> indexed by src
__device__ float g_agg[NMAX * H];    // message scatter target
__device__ float g_pos[NMAX * 3];
__device__ float g_dpos[NMAX * 3];
__device__ float g_wnode[NMAX];
__device__ unsigned g_wpack[560000]; // tf32-frag-packed weights (uint4-aligned)

// fast silu: 2 MUFU (EX2, RCP) + cheap ops; ~2ulp vs IEEE (negligible under tf32)
__device__ __forceinline__ float silu_f(float x) {
    float t = __expf(-x);
    return __fdividef(x, 1.0f + t);
}

__device__ __forceinline__ unsigned f2tf(float x) {
    unsigned r;
    asm("cvt.rna.tf32.f32 %0, %1;" : "=r"(r) : "f"(x));
    return r;
}

__device__ __forceinline__ float tfbits(float x) {
    return __uint_as_float(f2tf(x));
}

__device__ __forceinline__ void mma_tf32(float c[4], const unsigned a[4], const unsigned b[2]) {
    asm volatile(
        "mma.sync.aligned.m16n8k8.row.col.f32.tf32.tf32.f32 "
        "{%0,%1,%2,%3}, {%4,%5,%6,%7}, {%8,%9}, {%0,%1,%2,%3};"
        : "+f"(c[0]), "+f"(c[1]), "+f"(c[2]), "+f"(c[3])
        : "r"(a[0]), "r"(a[1]), "r"(a[2]), "r"(a[3]), "r"(b[0]), "r"(b[1]));
}

__device__ __forceinline__ void red_add_v4(float* addr, float a, float b, float c, float d) {
    asm volatile("red.global.add.v4.f32 [%0], {%1,%2,%3,%4};"
                 :: "l"(addr), "f"(a), "f"(b), "f"(c), "f"(d) : "memory");
}

// fragment-packed smem address for (row r in 0..63, k in 0..127)
__device__ __forceinline__ int fp_addr(int r, int k) {
    return ((r >> 4) * 16 + (k >> 3)) * FR + ((r & 7) * 4 + (k & 3)) * 4
         + ((r >> 3) & 1) + 2 * ((k >> 2) & 1);
}

// ---------------- generic weight fragment pack (once per launch) --------------
struct PackJobs {
    const float* src[28];
    unsigned dstOff[28];   // in uint4 units
    int blockOff[29];      // one block = one kk (256 threads)
    int njobs;
};

__global__ void packw_kernel(PackJobs jobs, unsigned* __restrict__ out) {
    int b = blockIdx.x;
    int j = 0;
    while (j + 1 < jobs.njobs && b >= jobs.blockOff[j + 1]) ++j;
    int kk = b - jobs.blockOff[j];
    const float* W = jobs.src[j];
    int tid = threadIdx.x;
    int wn = tid >> 5, lane = tid & 31;
    int g = lane >> 2, t = lane & 3;
    int ncol = wn * 16 + g;
    uint4 v;
    v.x = f2tf(W[(kk * 8 + t) * H + ncol]);
    v.y = f2tf(W[(kk * 8 + t + 4) * H + ncol]);
    v.z = f2tf(W[(kk * 8 + t) * H + ncol + 8]);
    v.w = f2tf(W[(kk * 8 + t + 4) * H + ncol + 8]);
    *(uint4*)(out + ((size_t)jobs.dstOff[j] + kk * 256 + wn * 32 + lane) * 4) = v;
}

// ---------------- GEMM building blocks (64-row tiles, 256 threads) ------------
// stage a 64-row x KS*8-col tile of src into frag-packed smem (row-paired STS.64)
template <int KS>
__device__ __forceinline__ void stage_tile(
    const float* __restrict__ src, int stride, int coff,
    float* Xs, int n, int row0)
{
    const int tid = threadIdx.x;
    constexpr int Q4 = KS * 2;
#pragma unroll
    for (int u = tid; u < 32 * Q4; u += 256) {
        int pr = u / Q4;
        int kq4 = u - pr * Q4;
        int q = pr >> 3, rr = pr & 7;
        int row = row0 + q * 16 + rr;
        int k0 = kq4 * 4;
        float4 v0 = make_float4(0.f, 0.f, 0.f, 0.f);
        float4 v1 = make_float4(0.f, 0.f, 0.f, 0.f);
        if (row < n)     v0 = *(const float4*)(src + (size_t)row * stride + coff + k0);
        if (row + 8 < n) v1 = *(const float4*)(src + (size_t)(row + 8) * stride + coff + k0);
        int base = (q * 16 + (k0 >> 3)) * FR + rr * 16 + 2 * ((k0 >> 2) & 1);
        *(float2*)(Xs + base + 0)  = make_float2(tfbits(v0.x), tfbits(v1.x));
        *(float2*)(Xs + base + 4)  = make_float2(tfbits(v0.y), tfbits(v1.y));
        *(float2*)(Xs + base + 8)  = make_float2(tfbits(v0.z), tfbits(v1.z));
        *(float2*)(Xs + base + 12) = make_float2(tfbits(v0.w), tfbits(v1.w));
    }
}

// MMA pass over staged fragments (KS k-steps), B stream from packed weights
template <int KS>
__device__ __forceinline__ void mma_pass(
    const uint4* __restrict__ Wp, int kc,
    float (&d)[2][4][4], const float* Xs, int rh, int cg, int lane)
{
    const uint4* wpb = Wp + ((size_t)(kc >> 3) * 8 + 2 * cg) * 32 + lane;
#pragma unroll
    for (int kk = 0; kk < KS; ++kk) {
        uint4 bva = __ldg(wpb + (size_t)kk * 256);
        uint4 bvb = __ldg(wpb + (size_t)kk * 256 + 32);
        unsigned bb[4][2] = {{bva.x, bva.y}, {bva.z, bva.w},
                             {bvb.x, bvb.y}, {bvb.z, bvb.w}};
#pragma unroll
        for (int mi = 0; mi < 2; ++mi) {
            int mt = rh * 2 + mi;
            float4 av = *(const float4*)(Xs + (mt * 16 + kk) * FR + lane * 4);
            unsigned a[4] = {__float_as_uint(av.x), __float_as_uint(av.y),
                             __float_as_uint(av.z), __float_as_uint(av.w)};
#pragma unroll
            for (int j = 0; j < 4; ++j) mma_tf32(d[mi][j], a, bb[j]);
        }
    }
}

template <int KS>
__device__ __forceinline__ void node_chunk64(
    const float* __restrict__ src, int stride, int coff, int kc,
    const uint4* __restrict__ Wp,
    float (&d)[2][4][4], float* Xs, int n, int row0)
{
    const int lane = threadIdx.x & 31;
    const int wn = threadIdx.x >> 5;
    __syncthreads();
    stage_tile<KS>(src, stride, coff, Xs, n, row0);
    __syncthreads();
    mma_pass<KS>(Wp, kc, d, Xs, wn >> 2, wn & 3, lane);
}

__device__ __forceinline__ void gemm_accum(
    const float* __restrict__ X1, int K1,
    const float* __restrict__ X2, int K2,
    const uint4* __restrict__ Wp,
    float (&d)[2][4][4], float* Xs, int n, int row0)
{
    const int Ktot = K1 + K2;
    for (int kc = 0; kc < Ktot; kc += 128) {
        const int kchunk = min(128, Ktot - kc);
        const float* src; int stride, coff;
        if (kc < K1) { src = X1; stride = K1; coff = kc; }
        else         { src = X2; stride = K2; coff = kc - K1; }
        if (kchunk == 128) node_chunk64<16>(src, stride, coff, kc, Wp, d, Xs, n, row0);
        else               node_chunk64<8>(src, stride, coff, kc, Wp, d, Xs, n, row0);
    }
}

__device__ __forceinline__ void zero_acc(float (&d)[2][4][4]) {
#pragma unroll
    for (int mi = 0; mi < 2; ++mi)
#pragma unroll
        for (int j = 0; j < 4; ++j)
#pragma unroll
            for (int s = 0; s < 4; ++s) d[mi][j][s] = 0.0f;
}

// ---------------- plain node GEMM (emb) ---------------------------------------
__global__ __launch_bounds__(256, 4) void node_gemm(
    const float* __restrict__ X1, int K1,
    const uint4* __restrict__ Wp,
    const float* __restrict__ bias,
    float* __restrict__ Y, int n)
{
    extern __shared__ float Xs[];
    const int tid = threadIdx.x;
    const int lane = tid & 31;
    const int wn = tid >> 5;
    const int rh = wn >> 2, cg = wn & 3;
    const int g = lane >> 2, t = lane & 3;
    const int row0 = blockIdx.x * 64;

    float d[2][4][4];
    zero_acc(d);
    gemm_accum(X1, K1, nullptr, 0, Wp, d, Xs, n, row0);

#pragma unroll
    for (int j = 0; j < 4; ++j) {
        const int col = cg * 32 + j * 8 + t * 2;
        float b0 = bias[col], b1v = bias[col + 1];
#pragma unroll
        for (int mi = 0; mi < 2; ++mi)
#pragma unroll
            for (int half = 0; half < 2; ++half) {
                int row = row0 + (rh * 2 + mi) * 16 + g + half * 8;
                if (row < n)
                    *(float2*)(Y + (size_t)row * H + col) = make_float2(
                        d[mi][j][half * 2 + 0] + b0, d[mi][j][half * 2 + 1] + b1v);
            }
    }
}

// ---------------- fused two-stage MLP kernel ----------------------------------
__global__ __launch_bounds__(256, 3) void fused_mlp(
    const float* __restrict__ X1, int K1,
    const float* __restrict__ X2, int K2,
    const uint4* __restrict__ Wp1, const float* __restrict__ b1,
    const uint4* __restrict__ Wp2, const float* __restrict__ b2,
    const float* __restrict__ res,
    float* __restrict__ Y, int n,
    float* __restrict__ zero_after)
{
    extern __shared__ float Xs[];
    const int tid = threadIdx.x;
    const int lane = tid & 31;
    const int wn = tid >> 5;
    const int rh = wn >> 2, cg = wn & 3;
    const int g = lane >> 2, t = lane & 3;
    const int row0 = blockIdx.x * 64;

    float d[2][4][4];
    zero_acc(d);
    gemm_accum(X1, K1, X2, K2, Wp1, d, Xs, n, row0);

    // stage-1 epilogue: silu -> frag-packed smem, row-paired STS.64
    __syncthreads();
#pragma unroll
    for (int j = 0; j < 4; ++j) {
        const int col = cg * 32 + j * 8 + t * 2;
        float b0 = b1[col], b1v = b1[col + 1];
#pragma unroll
        for (int mi = 0; mi < 2; ++mi) {
            int rl = (rh * 2 + mi) * 16 + g;
            *(float2*)(Xs + fp_addr(rl, col)) = make_float2(
                tfbits(silu_f(d[mi][j][0] + b0)),
                tfbits(silu_f(d[mi][j][2] + b0)));
            *(float2*)(Xs + fp_addr(rl, col + 1)) = make_float2(
                tfbits(silu_f(d[mi][j][1] + b1v)),
                tfbits(silu_f(d[mi][j][3] + b1v)));
        }
    }
    __syncthreads();

    zero_acc(d);
    mma_pass<16>(Wp2, 0, d, Xs, rh, cg, lane);

#pragma unroll
    for (int j = 0; j < 4; ++j) {
        const int col = cg * 32 + j * 8 + t * 2;
        float b0 = b2[col], b1v = b2[col + 1];
#pragma unroll
        for (int mi = 0; mi < 2; ++mi)
#pragma unroll
            for (int half = 0; half < 2; ++half) {
                int row = row0 + (rh * 2 + mi) * 16 + g + half * 8;
                if (row < n) {
                    float o0 = d[mi][j][half * 2 + 0] + b0;
                    float o1 = d[mi][j][half * 2 + 1] + b1v;
                    if (res) {
                        o0 += res[(size_t)row * H + col];
                        o1 += res[(size_t)row * H + col + 1];
                    }
                    *(float2*)(Y + (size_t)row * H + col) = make_float2(o0, o1);
                }
            }
    }

    if (zero_after) {
        const float4 z = make_float4(0.f, 0.f, 0.f, 0.f);
#pragma unroll
        for (int q = tid; q < 64 * 32; q += 256) {
            int r = q >> 5, c4 = q & 31;
            int row = row0 + r;
            if (row < n) *(float4*)(zero_after + (size_t)row * H + c4 * 4) = z;
        }
    }
}

// ---------------- fused3: stage h once; passes W1a->A, W1b->B, cW1->wnode -----
__global__ __launch_bounds__(256, 4) void fused3_gemm(
    const float* __restrict__ hbuf,
    const uint4* __restrict__ cW1p, const float* __restrict__ cB1,
    const float* __restrict__ cW2, const float* __restrict__ cb2,
    float* __restrict__ wnout,
    const uint4* __restrict__ W1ap, const float* __restrict__ aBias,
    const uint4* __restrict__ W1bp,
    float* __restrict__ A, float* __restrict__ B, int n)
{
    extern __shared__ float Xs[];
    const int tid = threadIdx.x;
    const int lane = tid & 31;
    const int wn = tid >> 5;
    const int rh = wn >> 2, cg = wn & 3;
    const int g = lane >> 2, t = lane & 3;
    const int row0 = blockIdx.x * 64;

    // stage h tile ONCE
    stage_tile<16>(hbuf, H, 0, Xs, n, row0);
    __syncthreads();

    float d[2][4][4];

    // ---- pass A: A = h @ W1a + msgB1 ----
    zero_acc(d);
    mma_pass<16>(W1ap, 0, d, Xs, rh, cg, lane);
#pragma unroll
    for (int j = 0; j < 4; ++j) {
        const int col = cg * 32 + j * 8 + t * 2;
        float b0 = aBias[col], b1v = aBias[col + 1];
#pragma unroll
        for (int mi = 0; mi < 2; ++mi)
#pragma unroll
            for (int half = 0; half < 2; ++half) {
                int row = row0 + (rh * 2 + mi) * 16 + g + half * 8;
                if (row < n)
                    *(float2*)(A + (size_t)row * H + col) = make_float2(
                        d[mi][j][half * 2 + 0] + b0, d[mi][j][half * 2 + 1] + b1v);
            }
    }

    // ---- pass B: B = h @ W1b ----
    zero_acc(d);
    mma_pass<16>(W1bp, 0, d, Xs, rh, cg, lane);
#pragma unroll
    for (int j = 0; j < 4; ++j) {
        const int col = cg * 32 + j * 8 + t * 2;
#pragma unroll
        for (int mi = 0; mi < 2; ++mi)
#pragma unroll
            for (int half = 0; half < 2; ++half) {
                int row = row0 + (rh * 2 + mi) * 16 + g + half * 8;
                if (row < n)
                    *(float2*)(B + (size_t)row * H + col) = make_float2(
                        d[mi][j][half * 2 + 0], d[mi][j][half * 2 + 1]);
            }
    }

    // ---- pass C: wnode = silu(h@cW1+cB1) . cW2 + cb2 (uses Xs as pad after) --
    zero_acc(d);
    mma_pass<16>(cW1p, 0, d, Xs, rh, cg, lane);
    float b0[4], b1v[4], w20[4], w21[4];
#pragma unroll
    for (int j = 0; j < 4; ++j) {
        const int col = cg * 32 + j * 8 + t * 2;
        b0[j] = cB1[col];
        b1v[j] = cB1[col + 1];
        w20[j] = cW2[col];
        w21[j] = cW2[col + 1];
    }
    __syncthreads();   // all warps done reading Xs fragments
#pragma unroll
    for (int mi = 0; mi < 2; ++mi) {
#pragma unroll
        for (int half = 0; half < 2; ++half) {
            int rl = (rh * 2 + mi) * 16 + g + half * 8;
            float s = 0.0f;
#pragma unroll
            for (int j = 0; j < 4; ++j) {
                float o0 = silu_f(d[mi][j][half * 2 + 0] + b0[j]);
                float o1 = silu_f(d[mi][j][half * 2 + 1] + b1v[j]);
                s = fmaf(o0, w20[j], fmaf(o1, w21[j], s));
            }
            s += __shfl_xor_sync(0xffffffffu, s, 1);
            s += __shfl_xor_sync(0xffffffffu, s, 2);
            if (t == 0) Xs[rl * 4 + cg] = s;
        }
    }
    __syncthreads();
    if (tid < 64) {
        float acc = cb2[0];
#pragma unroll
        for (int w = 0; w < 4; ++w) acc += Xs[tid * 4 + w];
        int row = row0 + tid;
        if (row < n) wnout[row] = acc;
    }
}

// ---------------- fused edge kernel (tf32 mma, 64-edge tiles, 256 thr, occ4) --
#define TE 64
__global__ __launch_bounds__(256, 4) void edge_kernel(
    const int* __restrict__ ei, int E, int Etot,
    const float* __restrict__ A, const float* __restrict__ B,
    const float* __restrict__ pos, const float* __restrict__ wnode,
    const unsigned* __restrict__ W2p,
    const float* __restrict__ b2, const float* __restrict__ w1c,
    float* __restrict__ agg, float* __restrict__ dpos)
{
    extern __shared__ float smbuf[];
    float* U = smbuf;                    // 64 frags * FR floats
    float* sdist = U + 64 * FR;          // 64
    int* ssrc = (int*)(sdist + TE);      // 64
    int* sdst = ssrc + TE;               // 64

    const int tid = threadIdx.x;
    const int lane = tid & 31;
    const int wn = tid >> 5;
    const int eh = wn >> 2;
    const int cg = wn & 3;
    const int g = lane >> 2, t = lane & 3;

    const int fq = lane;
    const float4 w1c4 = *(const float4*)(w1c + fq * 4);
    const int fragk = fq >> 1;
    const int slot2 = 2 * (fq & 1);
    float b2v[4][2];
#pragma unroll
    for (int j = 0; j < 4; ++j) {
        b2v[j][0] = b2[cg * 32 + j * 8 + t * 2];
        b2v[j][1] = b2[cg * 32 + j * 8 + t * 2 + 1];
    }
    const uint4* wpb = (const uint4*)W2p + (size_t)(2 * cg) * 32 + lane;

    const int ntiles = (Etot + TE - 1) / TE;
    for (int tile = blockIdx.x; tile < ntiles; tile += gridDim.x) {
        const int e0 = tile * TE;
        const int cnt = min(TE, Etot - e0);

        // ---- meta + coord update ----
        if (tid < TE) {
            int e = e0 + tid;
            int s = 0, dd = 0; float dist = 0.f;
            if (tid < cnt) {
                float rx, ry, rz;
                if (e < E) { s = ei[e]; dd = ei[E + e]; }
                else       { s = e - E; dd = s; }
                rx = pos[s * 3 + 0] - pos[dd * 3 + 0];
                ry = pos[s * 3 + 1] - pos[dd * 3 + 1];
                rz = pos[s * 3 + 2] - pos[dd * 3 + 2];
                dist = sqrtf(rx * rx + ry * ry + rz * rz);
                float inv = wnode[s] / (dist + EPS);
                atomicAdd(dpos + dd * 3 + 0, rx * inv);
                atomicAdd(dpos + dd * 3 + 1, ry * inv);
                atomicAdd(dpos + dd * 3 + 2, rz * inv);
            }
            ssrc[tid] = s; sdst[tid] = dd; sdist[tid] = dist;
        }
        __syncthreads();

        // ---- phase 1: u via LDG.128 gathers, edge-paired STS.64 staging ----
        {
            const int p0 = wn * 4;
#pragma unroll
            for (int i = 0; i < 4; ++i) {
                int p = p0 + i;
                int q = p >> 3, r = p & 7;
                int e = q * 16 + r;
                int sa = ssrc[e],     da = sdst[e];
                int sb = ssrc[e + 8], db = sdst[e + 8];
                float dist0 = sdist[e], dist1 = sdist[e + 8];
                float4 a0 = *(const float4*)(A + (size_t)da * H + fq * 4);
                float4 c0 = *(const float4*)(B + (size_t)sa * H + fq * 4);
                float4 a1 = *(const float4*)(A + (size_t)db * H + fq * 4);
                float4 c1 = *(const float4*)(B + (size_t)sb * H + fq * 4);
                int base = (q * 16 + fragk) * FR + r * 16 + slot2;
                *(float2*)(U + base + 0) = make_float2(
                    tfbits(silu_f(fmaf(dist0, w1c4.x, a0.x) + c0.x)),
                    tfbits(silu_f(fmaf(dist1, w1c4.x, a1.x) + c1.x)));
                *(float2*)(U + base + 4) = make_float2(
                    tfbits(silu_f(fmaf(dist0, w1c4.y, a0.y) + c0.y)),
                    tfbits(silu_f(fmaf(dist1, w1c4.y, a1.y) + c1.y)));
                *(float2*)(U + base + 8) = make_float2(
                    tfbits(silu_f(fmaf(dist0, w1c4.z, a0.z) + c0.z)),
                    tfbits(silu_f(fmaf(dist1, w1c4.z, a1.z) + c1.z)));
                *(float2*)(U + base + 12) = make_float2(
                    tfbits(silu_f(fmaf(dist0, w1c4.w, a0.w) + c0.w)),
                    tfbits(silu_f(fmaf(dist1, w1c4.w, a1.w) + c1.w)));
            }
        }
        __syncthreads();

        // ---- phase 2: tf32 mma, packed B via two LDG.128 per kk ----
        float acc[2][4][4];
#pragma unroll
        for (int mi = 0; mi < 2; ++mi)
#pragma unroll
            for (int j = 0; j < 4; ++j)
#pragma unroll
                for (int s = 0; s < 4; ++s) acc[mi][j][s] = 0.0f;

#pragma unroll
        for (int kk = 0; kk < 16; ++kk) {
            uint4 bva = __ldg(wpb + (size_t)kk * 256);
            uint4 bvb = __ldg(wpb + (size_t)kk * 256 + 32);
            unsigned bb[4][2] = {{bva.x, bva.y}, {bva.z, bva.w},
                                 {bvb.x, bvb.y}, {bvb.z, bvb.w}};
#pragma unroll
            for (int mi = 0; mi < 2; ++mi) {
                int mt = eh * 2 + mi;
                float4 av = *(const float4*)(U + (mt * 16 + kk) * FR + lane * 4);
                unsigned a[4] = {__float_as_uint(av.x), __float_as_uint(av.y),
                                 __float_as_uint(av.z), __float_as_uint(av.w)};
#pragma unroll
                for (int j = 0; j < 4; ++j) mma_tf32(acc[mi][j], a, bb[j]);
            }
        }

        // ---- phase 3: silu + shuffle-paired v4 scatter ----
#pragma unroll
        for (int mi = 0; mi < 2; ++mi) {
            const int e_lo = (eh * 2 + mi) * 16 + g;
            const int e_hi = e_lo + 8;
#pragma unroll
            for (int j = 0; j < 4; ++j) {
                float v0 = silu_f(acc[mi][j][0] + b2v[j][0]);
                float v1 = silu_f(acc[mi][j][1] + b2v[j][1]);
                float v2 = silu_f(acc[mi][j][2] + b2v[j][0]);
                float v3 = silu_f(acc[mi][j][3] + b2v[j][1]);
                float w0 = __shfl_xor_sync(0xffffffffu, v0, 1);
                float w1 = __shfl_xor_sync(0xffffffffu, v1, 1);
                float w2 = __shfl_xor_sync(0xffffffffu, v2, 1);
                float w3 = __shfl_xor_sync(0xffffffffu, v3, 1);
                if ((t & 1) == 0) {
                    const int col4 = cg * 32 + j * 8 + t * 2;
                    if (e_lo < cnt)
                        red_add_v4(agg + (size_t)sdst[e_lo] * H + col4, v0, v1, w0, w1);
                    if (e_hi < cnt)
                        red_add_v4(agg + (size_t)sdst[e_hi] * H + col4, v2, v3, w2, w3);
                }
            }
        }
        __syncthreads();
    }
}

// ---------------- small utility kernels --------------------------------------
__global__ void init_kernel(float* __restrict__ pos, const float* __restrict__ src,
                            float* __restrict__ dpos, int n3,
                            float* __restrict__ agg, int nagg) {
    int i = blockIdx.x * blockDim.x + threadIdx.x;
    if (i < n3) { pos[i] = src[i]; dpos[i] = 0.0f; }
    if (i < nagg) agg[i] = 0.0f;
}
__global__ void addzero_kernel(float* __restrict__ pos, float* __restrict__ dpos, int n3) {
    int i = blockIdx.x * blockDim.x + threadIdx.x;
    if (i < n3) { pos[i] += dpos[i]; dpos[i] = 0.0f; }
}
__global__ void copy_kernel(float* __restrict__ dst, const float* __restrict__ src, int n) {
    int i = blockIdx.x * blockDim.x + threadIdx.x;
    if (i < n) dst[i] = src[i];
}

// ---------------- host orchestration -----------------------------------------
extern "C" void kernel_launch(void* const* d_in, const int* in_sizes, int n_in,
                              void* d_out, int out_size)
{
    const float* h_in   = (const float*)d_in[0];
    const float* pos_in = (const float*)d_in[1];
    const int*   ei     = (const int*)d_in[2];
    const float* embW   = (const float*)d_in[3];
    const float* embB   = (const float*)d_in[4];
    const float* msgW1  = (const float*)d_in[5];
    const float* msgB1  = (const float*)d_in[6];
    const float* msgW2  = (const float*)d_in[7];
    const float* msgB2  = (const float*)d_in[8];
    const float* cW1    = (const float*)d_in[9];
    const float* cB1    = (const float*)d_in[10];
    const float* cW2    = (const float*)d_in[11];
    const float* cB2    = (const float*)d_in[12];
    const float* nW1    = (const float*)d_in[13];
    const float* nB1    = (const float*)d_in[14];
    const float* nW2    = (const float*)d_in[15];
    const float* nB2    = (const float*)d_in[16];
    const float* oW1    = (const float*)d_in[17];
    const float* oB1    = (const float*)d_in[18];
    const float* oW2    = (const float*)d_in[19];
    const float* oB2    = (const float*)d_in[20];

    const int N = in_sizes[1] / 3;
    const int E = in_sizes[2] / 2;
    const int Etot = E + N;
    const int INDIM = in_sizes[0] / N;

    float *bh, *bA, *bB, *bagg, *bpos, *bdpos, *bwn;
    unsigned* bwp;
    cudaGetSymbolAddress((void**)&bh, g_h);
    cudaGetSymbolAddress((void**)&bA, g_A);
    cudaGetSymbolAddress((void**)&bB, g_B);
    cudaGetSymbolAddress((void**)&bagg, g_agg);
    cudaGetSymbolAddress((void**)&bpos, g_pos);
    cudaGetSymbolAddress((void**)&bdpos, g_dpos);
    cudaGetSymbolAddress((void**)&bwn, g_wnode);
    cudaGetSymbolAddress((void**)&bwp, g_wpack);

    // ---- pack-job table ----
    PackJobs jobs;
    unsigned embOff, cW1Off[LAYERS], W1aOff[LAYERS], W1bOff[LAYERS];
    unsigned nW1Off[LAYERS], nW2Off[LAYERS], mW2Off[LAYERS], oW1Off, oW2Off;
    {
        int j = 0; unsigned off = 0; int boff = 0;
        auto add = [&](const float* src, int nkk, unsigned* offOut) {
            jobs.src[j] = src; jobs.dstOff[j] = off; jobs.blockOff[j] = boff;
            *offOut = off; off += (unsigned)nkk * 256; boff += nkk; ++j;
        };
        add(embW, INDIM / 8, &embOff);
        for (int l = 0; l < LAYERS; ++l) {
            add(cW1 + (size_t)l * H * H, 16, &cW1Off[l]);
            add(msgW1 + (size_t)l * 257 * H, 16, &W1aOff[l]);
            add(msgW1 + (size_t)l * 257 * H + 128 * H, 16, &W1bOff[l]);
            add(nW1 + (size_t)l * 2 * H * H, 32, &nW1Off[l]);
            add(nW2 + (size_t)l * H * H, 16, &nW2Off[l]);
            add(msgW2 + (size_t)l * H * H, 16, &mW2Off[l]);
        }
        add(oW1, 16, &oW1Off);
        add(oW2, 16, &oW2Off);
        jobs.njobs = j;
        jobs.blockOff[j] = boff;
        packw_kernel<<<boff, 256>>>(jobs, bwp);
    }
    const uint4* wp4 = (const uint4*)bwp;

    const int NODE_SMEM = 64 * FR * 4;                 // 33792 B
    const int EDGE_SMEM = 64 * FR * 4 + 3 * TE * 4;    // 34560 B (x4 = 138 KB)
    cudaFuncSetAttribute(node_gemm,
                         cudaFuncAttributeMaxDynamicSharedMemorySize, NODE_SMEM);
    cudaFuncSetAttribute(fused_mlp,
                         cudaFuncAttributeMaxDynamicSharedMemorySize, NODE_SMEM);
    cudaFuncSetAttribute(fused3_gemm,
                         cudaFuncAttributeMaxDynamicSharedMemorySize, NODE_SMEM);
    cudaFuncSetAttribute(edge_kernel,
                         cudaFuncAttributeMaxDynamicSharedMemorySize, EDGE_SMEM);

    const int gn = (N + 63) / 64;
    const int tinit = (N * H + 255) / 256;
    const int t256p = (N * 3 + 255) / 256;

    // embedding + pos/dpos/agg init
    node_gemm<<<gn, 256, NODE_SMEM>>>(h_in, INDIM, wp4 + embOff, embB, bh, N);
    init_kernel<<<tinit, 256>>>(bpos, pos_in, bdpos, N * 3, bagg, N * H);

    for (int l = 0; l < LAYERS; ++l) {
        const float* W1c = msgW1 + (size_t)l * 257 * H + 256 * H;

        fused3_gemm<<<gn, 256, NODE_SMEM>>>(
            bh, wp4 + cW1Off[l], cB1 + l * H, cW2 + (size_t)l * H, cB2 + l, bwn,
            wp4 + W1aOff[l], msgB1 + l * H, wp4 + W1bOff[l], bA, bB, N);

        edge_kernel<<<592, 256, EDGE_SMEM>>>(
            ei, E, Etot, bA, bB, bpos, bwn,
            (const unsigned*)(wp4 + mW2Off[l]), msgB2 + l * H, W1c,
            bagg, bdpos);

        fused_mlp<<<gn, 256, NODE_SMEM>>>(
            bh, H, bagg, H, wp4 + nW1Off[l], nB1 + l * H,
            wp4 + nW2Off[l], nB2 + l * H, bh, bh, N, bagg);
        addzero_kernel<<<t256p, 256>>>(bpos, bdpos, N * 3);
    }

    // fused output head
    fused_mlp<<<gn, 256, NODE_SMEM>>>(
        bh, H, nullptr, 0, wp4 + oW1Off, oB1,
        wp4 + oW2Off, oB2, nullptr, (float*)d_out, N, nullptr);

    if (out_size >= N * H + N * 3) {
        copy_kernel<<<t256p, 256>>>((float*)d_out + (size_t)N * H, bpos, N * 3);
    }
}

// round 17
// speedup vs baseline: 1.0538x; 1.0538x over previous
#include <cuda_runtime.h>
#include <math.h>

#define H 128
#define LAYERS 4
#define NMAX 50176
#define EPS 1e-8f
#define FR 132   // fragment-pack stride in floats (2-way-conflict choice)

// ---------------- static device scratch (allocation-free rule) ----------------
__device__ float g_h[NMAX * H];
__device__ float g_A[NMAX * H];      // (h @ msgW1[0:128] + msgB1) -> indexed by dst
__device__ float g_B[NMAX * H];      // (h @ msgW1[128:256])       -> indexed by src
__device__ float g_agg[NMAX * H];    // message scatter target
__device__ float g_pos[NMAX * 3];
__device__ float g_dpos[NMAX * 3];
__device__ float g_wnode[NMAX];
__device__ unsigned g_wpack[560000]; // tf32-frag-packed weights (uint4-aligned)

// fast silu: 2 MUFU (EX2, RCP) + cheap ops; ~2ulp vs IEEE (negligible under tf32)
__device__ __forceinline__ float silu_f(float x) {
    float t = __expf(-x);
    return __fdividef(x, 1.0f + t);
}

__device__ __forceinline__ unsigned f2tf(float x) {
    unsigned r;
    asm("cvt.rna.tf32.f32 %0, %1;" : "=r"(r) : "f"(x));
    return r;
}

__device__ __forceinline__ float tfbits(float x) {
    return __uint_as_float(f2tf(x));
}

__device__ __forceinline__ void mma_tf32(float c[4], const unsigned a[4], const unsigned b[2]) {
    asm volatile(
        "mma.sync.aligned.m16n8k8.row.col.f32.tf32.tf32.f32 "
        "{%0,%1,%2,%3}, {%4,%5,%6,%7}, {%8,%9}, {%0,%1,%2,%3};"
        : "+f"(c[0]), "+f"(c[1]), "+f"(c[2]), "+f"(c[3])
        : "r"(a[0]), "r"(a[1]), "r"(a[2]), "r"(a[3]), "r"(b[0]), "r"(b[1]));
}

__device__ __forceinline__ void red_add_v4(float* addr, float a, float b, float c, float d) {
    asm volatile("red.global.add.v4.f32 [%0], {%1,%2,%3,%4};"
                 :: "l"(addr), "f"(a), "f"(b), "f"(c), "f"(d) : "memory");
}

// fragment-packed smem address for (row r in 0..63, k in 0..127)
__device__ __forceinline__ int fp_addr(int r, int k) {
    return ((r >> 4) * 16 + (k >> 3)) * FR + ((r & 7) * 4 + (k & 3)) * 4
         + ((r >> 3) & 1) + 2 * ((k >> 2) & 1);
}

// ---------------- generic weight fragment pack (once per launch) --------------
struct PackJobs {
    const float* src[28];
    unsigned dstOff[28];   // in uint4 units
    int blockOff[29];      // one block = one kk (256 threads)
    int njobs;
};

__global__ void packw_kernel(PackJobs jobs, unsigned* __restrict__ out) {
    int b = blockIdx.x;
    int j = 0;
    while (j + 1 < jobs.njobs && b >= jobs.blockOff[j + 1]) ++j;
    int kk = b - jobs.blockOff[j];
    const float* W = jobs.src[j];
    int tid = threadIdx.x;
    int wn = tid >> 5, lane = tid & 31;
    int g = lane >> 2, t = lane & 3;
    int ncol = wn * 16 + g;
    uint4 v;
    v.x = f2tf(W[(kk * 8 + t) * H + ncol]);
    v.y = f2tf(W[(kk * 8 + t + 4) * H + ncol]);
    v.z = f2tf(W[(kk * 8 + t) * H + ncol + 8]);
    v.w = f2tf(W[(kk * 8 + t + 4) * H + ncol + 8]);
    *(uint4*)(out + ((size_t)jobs.dstOff[j] + kk * 256 + wn * 32 + lane) * 4) = v;
}

// ---------------- GEMM building blocks (64-row tiles, 256 threads) ------------
template <int KS>
__device__ __forceinline__ void stage_tile(
    const float* __restrict__ src, int stride, int coff,
    float* Xs, int n, int row0)
{
    const int tid = threadIdx.x;
    constexpr int Q4 = KS * 2;
#pragma unroll
    for (int u = tid; u < 32 * Q4; u += 256) {
        int pr = u / Q4;
        int kq4 = u - pr * Q4;
        int q = pr >> 3, rr = pr & 7;
        int row = row0 + q * 16 + rr;
        int k0 = kq4 * 4;
        float4 v0 = make_float4(0.f, 0.f, 0.f, 0.f);
        float4 v1 = make_float4(0.f, 0.f, 0.f, 0.f);
        if (row < n)     v0 = *(const float4*)(src + (size_t)row * stride + coff + k0);
        if (row + 8 < n) v1 = *(const float4*)(src + (size_t)(row + 8) * stride + coff + k0);
        int base = (q * 16 + (k0 >> 3)) * FR + rr * 16 + 2 * ((k0 >> 2) & 1);
        *(float2*)(Xs + base + 0)  = make_float2(tfbits(v0.x), tfbits(v1.x));
        *(float2*)(Xs + base + 4)  = make_float2(tfbits(v0.y), tfbits(v1.y));
        *(float2*)(Xs + base + 8)  = make_float2(tfbits(v0.z), tfbits(v1.z));
        *(float2*)(Xs + base + 12) = make_float2(tfbits(v0.w), tfbits(v1.w));
    }
}

template <int KS>
__device__ __forceinline__ void mma_pass(
    const uint4* __restrict__ Wp, int kc,
    float (&d)[2][4][4], const float* Xs, int rh, int cg, int lane)
{
    const uint4* wpb = Wp + ((size_t)(kc >> 3) * 8 + 2 * cg) * 32 + lane;
#pragma unroll
    for (int kk = 0; kk < KS; ++kk) {
        uint4 bva = __ldg(wpb + (size_t)kk * 256);
        uint4 bvb = __ldg(wpb + (size_t)kk * 256 + 32);
        unsigned bb[4][2] = {{bva.x, bva.y}, {bva.z, bva.w},
                             {bvb.x, bvb.y}, {bvb.z, bvb.w}};
#pragma unroll
        for (int mi = 0; mi < 2; ++mi) {
            int mt = rh * 2 + mi;
            float4 av = *(const float4*)(Xs + (mt * 16 + kk) * FR + lane * 4);
            unsigned a[4] = {__float_as_uint(av.x), __float_as_uint(av.y),
                             __float_as_uint(av.z), __float_as_uint(av.w)};
#pragma unroll
            for (int j = 0; j < 4; ++j) mma_tf32(d[mi][j], a, bb[j]);
        }
    }
}

template <int KS>
__device__ __forceinline__ void node_chunk64(
    const float* __restrict__ src, int stride, int coff, int kc,
    const uint4* __restrict__ Wp,
    float (&d)[2][4][4], float* Xs, int n, int row0)
{
    const int lane = threadIdx.x & 31;
    const int wn = threadIdx.x >> 5;
    __syncthreads();
    stage_tile<KS>(src, stride, coff, Xs, n, row0);
    __syncthreads();
    mma_pass<KS>(Wp, kc, d, Xs, wn >> 2, wn & 3, lane);
}

__device__ __forceinline__ void gemm_accum(
    const float* __restrict__ X1, int K1,
    const float* __restrict__ X2, int K2,
    const uint4* __restrict__ Wp,
    float (&d)[2][4][4], float* Xs, int n, int row0)
{
    const int Ktot = K1 + K2;
    for (int kc = 0; kc < Ktot; kc += 128) {
        const int kchunk = min(128, Ktot - kc);
        const float* src; int stride, coff;
        if (kc < K1) { src = X1; stride = K1; coff = kc; }
        else         { src = X2; stride = K2; coff = kc - K1; }
        if (kchunk == 128) node_chunk64<16>(src, stride, coff, kc, Wp, d, Xs, n, row0);
        else               node_chunk64<8>(src, stride, coff, kc, Wp, d, Xs, n, row0);
    }
}

__device__ __forceinline__ void zero_acc(float (&d)[2][4][4]) {
#pragma unroll
    for (int mi = 0; mi < 2; ++mi)
#pragma unroll
        for (int j = 0; j < 4; ++j)
#pragma unroll
            for (int s = 0; s < 4; ++s) d[mi][j][s] = 0.0f;
}

// ---------------- plain node GEMM (emb) ---------------------------------------
__global__ __launch_bounds__(256, 4) void node_gemm(
    const float* __restrict__ X1, int K1,
    const uint4* __restrict__ Wp,
    const float* __restrict__ bias,
    float* __restrict__ Y, int n)
{
    extern __shared__ float Xs[];
    const int tid = threadIdx.x;
    const int lane = tid & 31;
    const int wn = tid >> 5;
    const int rh = wn >> 2, cg = wn & 3;
    const int g = lane >> 2, t = lane & 3;
    const int row0 = blockIdx.x * 64;

    float d[2][4][4];
    zero_acc(d);
    gemm_accum(X1, K1, nullptr, 0, Wp, d, Xs, n, row0);

#pragma unroll
    for (int j = 0; j < 4; ++j) {
        const int col = cg * 32 + j * 8 + t * 2;
        float b0 = bias[col], b1v = bias[col + 1];
#pragma unroll
        for (int mi = 0; mi < 2; ++mi)
#pragma unroll
            for (int half = 0; half < 2; ++half) {
                int row = row0 + (rh * 2 + mi) * 16 + g + half * 8;
                if (row < n)
                    *(float2*)(Y + (size_t)row * H + col) = make_float2(
                        d[mi][j][half * 2 + 0] + b0, d[mi][j][half * 2 + 1] + b1v);
            }
    }
}

// ---------------- fused two-stage MLP kernel (+ optional pos update) ----------
__global__ __launch_bounds__(256, 3) void fused_mlp(
    const float* __restrict__ X1, int K1,
    const float* __restrict__ X2, int K2,
    const uint4* __restrict__ Wp1, const float* __restrict__ b1,
    const uint4* __restrict__ Wp2, const float* __restrict__ b2,
    const float* __restrict__ res,
    float* __restrict__ Y, int n,
    float* __restrict__ zero_after,
    float* __restrict__ pos, float* __restrict__ dpos)
{
    extern __shared__ float Xs[];
    const int tid = threadIdx.x;
    const int lane = tid & 31;
    const int wn = tid >> 5;
    const int rh = wn >> 2, cg = wn & 3;
    const int g = lane >> 2, t = lane & 3;
    const int row0 = blockIdx.x * 64;

    float d[2][4][4];
    zero_acc(d);
    gemm_accum(X1, K1, X2, K2, Wp1, d, Xs, n, row0);

    // stage-1 epilogue: silu -> frag-packed smem, row-paired STS.64
    __syncthreads();
#pragma unroll
    for (int j = 0; j < 4; ++j) {
        const int col = cg * 32 + j * 8 + t * 2;
        float b0 = b1[col], b1v = b1[col + 1];
#pragma unroll
        for (int mi = 0; mi < 2; ++mi) {
            int rl = (rh * 2 + mi) * 16 + g;
            *(float2*)(Xs + fp_addr(rl, col)) = make_float2(
                tfbits(silu_f(d[mi][j][0] + b0)),
                tfbits(silu_f(d[mi][j][2] + b0)));
            *(float2*)(Xs + fp_addr(rl, col + 1)) = make_float2(
                tfbits(silu_f(d[mi][j][1] + b1v)),
                tfbits(silu_f(d[mi][j][3] + b1v)));
        }
    }
    __syncthreads();

    zero_acc(d);
    mma_pass<16>(Wp2, 0, d, Xs, rh, cg, lane);

#pragma unroll
    for (int j = 0; j < 4; ++j) {
        const int col = cg * 32 + j * 8 + t * 2;
        float b0 = b2[col], b1v = b2[col + 1];
#pragma unroll
        for (int mi = 0; mi < 2; ++mi)
#pragma unroll
            for (int half = 0; half < 2; ++half) {
                int row = row0 + (rh * 2 + mi) * 16 + g + half * 8;
                if (row < n) {
                    float o0 = d[mi][j][half * 2 + 0] + b0;
                    float o1 = d[mi][j][half * 2 + 1] + b1v;
                    if (res) {
                        o0 += res[(size_t)row * H + col];
                        o1 += res[(size_t)row * H + col + 1];
                    }
                    *(float2*)(Y + (size_t)row * H + col) = make_float2(o0, o1);
                }
            }
    }

    if (zero_after) {
        const float4 z = make_float4(0.f, 0.f, 0.f, 0.f);
#pragma unroll
        for (int q = tid; q < 64 * 32; q += 256) {
            int r = q >> 5, c4 = q & 31;
            int row = row0 + r;
            if (row < n) *(float4*)(zero_after + (size_t)row * H + c4 * 4) = z;
        }
    }

    // fused pos update for this block's rows (race-free: runs after edge kernel)
    if (pos && tid < 192) {
        int idx = row0 * 3 + tid;
        if (idx < n * 3) {
            pos[idx] += dpos[idx];
            dpos[idx] = 0.0f;
        }
    }
}

// ---------------- fused3: wnode + A(+msgB1) + B (3-way block split) -----------
__global__ __launch_bounds__(256, 3) void fused3_gemm(
    const float* __restrict__ hbuf,
    const uint4* __restrict__ cW1p, const float* __restrict__ cB1,
    const float* __restrict__ cW2, const float* __restrict__ cb2,
    float* __restrict__ wnout,
    const uint4* __restrict__ W1ap, const float* __restrict__ aBias,
    const uint4* __restrict__ W1bp,
    float* __restrict__ A, float* __restrict__ B, int n)
{
    extern __shared__ float Xs[];
    const int tid = threadIdx.x;
    const int lane = tid & 31;
    const int wn = tid >> 5;
    const int rh = wn >> 2, cg = wn & 3;
    const int g = lane >> 2, t = lane & 3;
    const int row0 = blockIdx.x * 64;

    float d[2][4][4];
    zero_acc(d);

    if (blockIdx.y == 0) {
        gemm_accum(hbuf, H, nullptr, 0, cW1p, d, Xs, n, row0);
        float b0[4], b1v[4], w20[4], w21[4];
#pragma unroll
        for (int j = 0; j < 4; ++j) {
            const int col = cg * 32 + j * 8 + t * 2;
            b0[j] = cB1[col];
            b1v[j] = cB1[col + 1];
            w20[j] = cW2[col];
            w21[j] = cW2[col + 1];
        }
        __syncthreads();
#pragma unroll
        for (int mi = 0; mi < 2; ++mi) {
#pragma unroll
            for (int half = 0; half < 2; ++half) {
                int rl = (rh * 2 + mi) * 16 + g + half * 8;
                float s = 0.0f;
#pragma unroll
                for (int j = 0; j < 4; ++j) {
                    float o0 = silu_f(d[mi][j][half * 2 + 0] + b0[j]);
                    float o1 = silu_f(d[mi][j][half * 2 + 1] + b1v[j]);
                    s = fmaf(o0, w20[j], fmaf(o1, w21[j], s));
                }
                s += __shfl_xor_sync(0xffffffffu, s, 1);
                s += __shfl_xor_sync(0xffffffffu, s, 2);
                if (t == 0) Xs[rl * 4 + cg] = s;
            }
        }
        __syncthreads();
        if (tid < 64) {
            float acc = cb2[0];
#pragma unroll
            for (int w = 0; w < 4; ++w) acc += Xs[tid * 4 + w];
            int row = row0 + tid;
            if (row < n) wnout[row] = acc;
        }
        return;
    }

    const bool isA = (blockIdx.y == 1);
    const uint4* Wp = isA ? W1ap : W1bp;
    float* Y = isA ? A : B;
    gemm_accum(hbuf, H, nullptr, 0, Wp, d, Xs, n, row0);
#pragma unroll
    for (int j = 0; j < 4; ++j) {
        const int col = cg * 32 + j * 8 + t * 2;
        float b0 = isA ? aBias[col] : 0.0f;
        float b1v = isA ? aBias[col + 1] : 0.0f;
#pragma unroll
        for (int mi = 0; mi < 2; ++mi)
#pragma unroll
            for (int half = 0; half < 2; ++half) {
                int row = row0 + (rh * 2 + mi) * 16 + g + half * 8;
                if (row < n)
                    *(float2*)(Y + (size_t)row * H + col) = make_float2(
                        d[mi][j][half * 2 + 0] + b0, d[mi][j][half * 2 + 1] + b1v);
            }
    }
}

// ---------------- fused edge kernel (tf32 mma, 64-edge tiles, 256 thr, occ4) --
#define TE 64
__global__ __launch_bounds__(256, 4) void edge_kernel(
    const int* __restrict__ ei, int E, int Etot,
    const float* __restrict__ A, const float* __restrict__ B,
    const float* __restrict__ pos, const float* __restrict__ wnode,
    const unsigned* __restrict__ W2p,
    const float* __restrict__ b2, const float* __restrict__ w1c,
    float* __restrict__ agg, float* __restrict__ dpos)
{
    extern __shared__ float smbuf[];
    float* U = smbuf;                    // 64 frags * FR floats
    float* sdist = U + 64 * FR;          // 64
    int* ssrc = (int*)(sdist + TE);      // 64
    int* sdst = ssrc + TE;               // 64

    const int tid = threadIdx.x;
    const int lane = tid & 31;
    const int wn = tid >> 5;
    const int eh = wn >> 2;
    const int cg = wn & 3;
    const int g = lane >> 2, t = lane & 3;

    const int fq = lane;
    const float4 w1c4 = *(const float4*)(w1c + fq * 4);
    const int fragk = fq >> 1;
    const int slot2 = 2 * (fq & 1);
    float b2v[4][2];
#pragma unroll
    for (int j = 0; j < 4; ++j) {
        b2v[j][0] = b2[cg * 32 + j * 8 + t * 2];
        b2v[j][1] = b2[cg * 32 + j * 8 + t * 2 + 1];
    }
    const uint4* wpb = (const uint4*)W2p + (size_t)(2 * cg) * 32 + lane;

    const int ntiles = (Etot + TE - 1) / TE;
    for (int tile = blockIdx.x; tile < ntiles; tile += gridDim.x) {
        const int e0 = tile * TE;
        const int cnt = min(TE, Etot - e0);

        // ---- meta + coord update ----
        if (tid < TE) {
            int e = e0 + tid;
            int s = 0, dd = 0; float dist = 0.f;
            if (tid < cnt) {
                float rx, ry, rz;
                if (e < E) { s = ei[e]; dd = ei[E + e]; }
                else       { s = e - E; dd = s; }
                rx = pos[s * 3 + 0] - pos[dd * 3 + 0];
                ry = pos[s * 3 + 1] - pos[dd * 3 + 1];
                rz = pos[s * 3 + 2] - pos[dd * 3 + 2];
                dist = sqrtf(rx * rx + ry * ry + rz * rz);
                float inv = wnode[s] / (dist + EPS);
                atomicAdd(dpos + dd * 3 + 0, rx * inv);
                atomicAdd(dpos + dd * 3 + 1, ry * inv);
                atomicAdd(dpos + dd * 3 + 2, rz * inv);
            }
            ssrc[tid] = s; sdst[tid] = dd; sdist[tid] = dist;
        }
        __syncthreads();

        // ---- phase 1: u via LDG.128 gathers, edge-paired STS.64 staging ----
        {
            const int p0 = wn * 4;
#pragma unroll
            for (int i = 0; i < 4; ++i) {
                int p = p0 + i;
                int q = p >> 3, r = p & 7;
                int e = q * 16 + r;
                int sa = ssrc[e],     da = sdst[e];
                int sb = ssrc[e + 8], db = sdst[e + 8];
                float dist0 = sdist[e], dist1 = sdist[e + 8];
                float4 a0 = *(const float4*)(A + (size_t)da * H + fq * 4);
                float4 c0 = *(const float4*)(B + (size_t)sa * H + fq * 4);
                float4 a1 = *(const float4*)(A + (size_t)db * H + fq * 4);
                float4 c1 = *(const float4*)(B + (size_t)sb * H + fq * 4);
                int base = (q * 16 + fragk) * FR + r * 16 + slot2;
                *(float2*)(U + base + 0) = make_float2(
                    tfbits(silu_f(fmaf(dist0, w1c4.x, a0.x) + c0.x)),
                    tfbits(silu_f(fmaf(dist1, w1c4.x, a1.x) + c1.x)));
                *(float2*)(U + base + 4) = make_float2(
                    tfbits(silu_f(fmaf(dist0, w1c4.y, a0.y) + c0.y)),
                    tfbits(silu_f(fmaf(dist1, w1c4.y, a1.y) + c1.y)));
                *(float2*)(U + base + 8) = make_float2(
                    tfbits(silu_f(fmaf(dist0, w1c4.z, a0.z) + c0.z)),
                    tfbits(silu_f(fmaf(dist1, w1c4.z, a1.z) + c1.z)));
                *(float2*)(U + base + 12) = make_float2(
                    tfbits(silu_f(fmaf(dist0, w1c4.w, a0.w) + c0.w)),
                    tfbits(silu_f(fmaf(dist1, w1c4.w, a1.w) + c1.w)));
            }
        }
        __syncthreads();

        // ---- phase 2: tf32 mma, packed B via two LDG.128 per kk ----
        float acc[2][4][4];
#pragma unroll
        for (int mi = 0; mi < 2; ++mi)
#pragma unroll
            for (int j = 0; j < 4; ++j)
#pragma unroll
                for (int s = 0; s < 4; ++s) acc[mi][j][s] = 0.0f;

#pragma unroll
        for (int kk = 0; kk < 16; ++kk) {
            uint4 bva = __ldg(wpb + (size_t)kk * 256);
            uint4 bvb = __ldg(wpb + (size_t)kk * 256 + 32);
            unsigned bb[4][2] = {{bva.x, bva.y}, {bva.z, bva.w},
                                 {bvb.x, bvb.y}, {bvb.z, bvb.w}};
#pragma unroll
            for (int mi = 0; mi < 2; ++mi) {
                int mt = eh * 2 + mi;
                float4 av = *(const float4*)(U + (mt * 16 + kk) * FR + lane * 4);
                unsigned a[4] = {__float_as_uint(av.x), __float_as_uint(av.y),
                                 __float_as_uint(av.z), __float_as_uint(av.w)};
#pragma unroll
                for (int j = 0; j < 4; ++j) mma_tf32(acc[mi][j], a, bb[j]);
            }
        }

        // ---- phase 3: silu + shuffle-paired v4 scatter ----
#pragma unroll
        for (int mi = 0; mi < 2; ++mi) {
            const int e_lo = (eh * 2 + mi) * 16 + g;
            const int e_hi = e_lo + 8;
#pragma unroll
            for (int j = 0; j < 4; ++j) {
                float v0 = silu_f(acc[mi][j][0] + b2v[j][0]);
                float v1 = silu_f(acc[mi][j][1] + b2v[j][1]);
                float v2 = silu_f(acc[mi][j][2] + b2v[j][0]);
                float v3 = silu_f(acc[mi][j][3] + b2v[j][1]);
                float w0 = __shfl_xor_sync(0xffffffffu, v0, 1);
                float w1 = __shfl_xor_sync(0xffffffffu, v1, 1);
                float w2 = __shfl_xor_sync(0xffffffffu, v2, 1);
                float w3 = __shfl_xor_sync(0xffffffffu, v3, 1);
                if ((t & 1) == 0) {
                    const int col4 = cg * 32 + j * 8 + t * 2;
                    if (e_lo < cnt)
                        red_add_v4(agg + (size_t)sdst[e_lo] * H + col4, v0, v1, w0, w1);
                    if (e_hi < cnt)
                        red_add_v4(agg + (size_t)sdst[e_hi] * H + col4, v2, v3, w2, w3);
                }
            }
        }
        __syncthreads();
    }
}

// ---------------- small utility kernels --------------------------------------
__global__ void init_kernel(float* __restrict__ pos, const float* __restrict__ src,
                            float* __restrict__ dpos, int n3,
                            float* __restrict__ agg, int nagg) {
    int i = blockIdx.x * blockDim.x + threadIdx.x;
    if (i < n3) { pos[i] = src[i]; dpos[i] = 0.0f; }
    if (i < nagg) agg[i] = 0.0f;
}
__global__ void copy_kernel(float* __restrict__ dst, const float* __restrict__ src, int n) {
    int i = blockIdx.x * blockDim.x + threadIdx.x;
    if (i < n) dst[i] = src[i];
}

// ---------------- host orchestration -----------------------------------------
extern "C" void kernel_launch(void* const* d_in, const int* in_sizes, int n_in,
                              void* d_out, int out_size)
{
    const float* h_in   = (const float*)d_in[0];
    const float* pos_in = (const float*)d_in[1];
    const int*   ei     = (const int*)d_in[2];
    const float* embW   = (const float*)d_in[3];
    const float* embB   = (const float*)d_in[4];
    const float* msgW1  = (const float*)d_in[5];
    const float* msgB1  = (const float*)d_in[6];
    const float* msgW2  = (const float*)d_in[7];
    const float* msgB2  = (const float*)d_in[8];
    const float* cW1    = (const float*)d_in[9];
    const float* cB1    = (const float*)d_in[10];
    const float* cW2    = (const float*)d_in[11];
    const float* cB2    = (const float*)d_in[12];
    const float* nW1    = (const float*)d_in[13];
    const float* nB1    = (const float*)d_in[14];
    const float* nW2    = (const float*)d_in[15];
    const float* nB2    = (const float*)d_in[16];
    const float* oW1    = (const float*)d_in[17];
    const float* oB1    = (const float*)d_in[18];
    const float* oW2    = (const float*)d_in[19];
    const float* oB2    = (const float*)d_in[20];

    const int N = in_sizes[1] / 3;
    const int E = in_sizes[2] / 2;
    const int Etot = E + N;
    const int INDIM = in_sizes[0] / N;

    float *bh, *bA, *bB, *bagg, *bpos, *bdpos, *bwn;
    unsigned* bwp;
    cudaGetSymbolAddress((void**)&bh, g_h);
    cudaGetSymbolAddress((void**)&bA, g_A);
    cudaGetSymbolAddress((void**)&bB, g_B);
    cudaGetSymbolAddress((void**)&bagg, g_agg);
    cudaGetSymbolAddress((void**)&bpos, g_pos);
    cudaGetSymbolAddress((void**)&bdpos, g_dpos);
    cudaGetSymbolAddress((void**)&bwn, g_wnode);
    cudaGetSymbolAddress((void**)&bwp, g_wpack);

    // ---- pack-job table ----
    PackJobs jobs;
    unsigned embOff, cW1Off[LAYERS], W1aOff[LAYERS], W1bOff[LAYERS];
    unsigned nW1Off[LAYERS], nW2Off[LAYERS], mW2Off[LAYERS], oW1Off, oW2Off;
    {
        int j = 0; unsigned off = 0; int boff = 0;
        auto add = [&](const float* src, int nkk, unsigned* offOut) {
            jobs.src[j] = src; jobs.dstOff[j] = off; jobs.blockOff[j] = boff;
            *offOut = off; off += (unsigned)nkk * 256; boff += nkk; ++j;
        };
        add(embW, INDIM / 8, &embOff);
        for (int l = 0; l < LAYERS; ++l) {
            add(cW1 + (size_t)l * H * H, 16, &cW1Off[l]);
            add(msgW1 + (size_t)l * 257 * H, 16, &W1aOff[l]);
            add(msgW1 + (size_t)l * 257 * H + 128 * H, 16, &W1bOff[l]);
            add(nW1 + (size_t)l * 2 * H * H, 32, &nW1Off[l]);
            add(nW2 + (size_t)l * H * H, 16, &nW2Off[l]);
            add(msgW2 + (size_t)l * H * H, 16, &mW2Off[l]);
        }
        add(oW1, 16, &oW1Off);
        add(oW2, 16, &oW2Off);
        jobs.njobs = j;
        jobs.blockOff[j] = boff;
        packw_kernel<<<boff, 256>>>(jobs, bwp);
    }
    const uint4* wp4 = (const uint4*)bwp;

    const int NODE_SMEM = 64 * FR * 4;                 // 33792 B
    const int EDGE_SMEM = 64 * FR * 4 + 3 * TE * 4;    // 34560 B (x4 = 138 KB)
    cudaFuncSetAttribute(node_gemm,
                         cudaFuncAttributeMaxDynamicSharedMemorySize, NODE_SMEM);
    cudaFuncSetAttribute(fused_mlp,
                         cudaFuncAttributeMaxDynamicSharedMemorySize, NODE_SMEM);
    cudaFuncSetAttribute(fused3_gemm,
                         cudaFuncAttributeMaxDynamicSharedMemorySize, NODE_SMEM);
    cudaFuncSetAttribute(edge_kernel,
                         cudaFuncAttributeMaxDynamicSharedMemorySize, EDGE_SMEM);

    const int gn = (N + 63) / 64;
    const int tinit = (N * H + 255) / 256;
    const int t256p = (N * 3 + 255) / 256;

    // embedding + pos/dpos/agg init
    node_gemm<<<gn, 256, NODE_SMEM>>>(h_in, INDIM, wp4 + embOff, embB, bh, N);
    init_kernel<<<tinit, 256>>>(bpos, pos_in, bdpos, N * 3, bagg, N * H);

    for (int l = 0; l < LAYERS; ++l) {
        const float* W1c = msgW1 + (size_t)l * 257 * H + 256 * H;

        fused3_gemm<<<dim3(gn, 3), 256, NODE_SMEM>>>(
            bh, wp4 + cW1Off[l], cB1 + l * H, cW2 + (size_t)l * H, cB2 + l, bwn,
            wp4 + W1aOff[l], msgB1 + l * H, wp4 + W1bOff[l], bA, bB, N);

        edge_kernel<<<592, 256, EDGE_SMEM>>>(
            ei, E, Etot, bA, bB, bpos, bwn,
            (const unsigned*)(wp4 + mW2Off[l]), msgB2 + l * H, W1c,
            bagg, bdpos);

        // node MLP + residual + agg re-zero + pos update (all fused)
        fused_mlp<<<gn, 256, NODE_SMEM>>>(
            bh, H, bagg, H, wp4 + nW1Off[l], nB1 + l * H,
            wp4 + nW2Off[l], nB2 + l * H, bh, bh, N, bagg, bpos, bdpos);
    }

    // fused output head
    fused_mlp<<<gn, 256, NODE_SMEM>>>(
        bh, H, nullptr, 0, wp4 + oW1Off, oB1,
        wp4 + oW2Off, oB2, nullptr, (float*)d_out, N, nullptr, nullptr, nullptr);

    if (out_size >= N * H + N * 3) {
        copy_kernel<<<t256p, 256>>>((float*)d_out + (size_t)N * H, bpos, N * 3);
    }
}